// round 3
// baseline (speedup 1.0000x reference)
#include <cuda_runtime.h>
#include <cuda_bf16.h>
#include <cstdint>

// Problem: out[v][g][u][d] = W[GE[v][g] % 3][d] + b[d]
//   V=512, G=4, D=64, out shape [V,G,V,D] fp32 = 256 MB (write-bound).
//
// NOTE: GE is int32 on-device (JAX x64 disabled => jnp.int64 falls back
// to int32). Reading it as int64 was the round-1 bug.
//
// Grid: one block per (v,g) pair -> 2048 blocks, 256 threads.
// Each thread computes one float4 of the 64-float emb row and stores it
// 32 times (u = tid/16 + 16*k), fully coalesced STG.128.

static constexpr int V = 512;
static constexpr int G = 4;
static constexpr int D = 64;
static constexpr int DQ = D / 4;          // 16 float4 per row
static constexpr int ROW_F4 = V * DQ;     // 8192 float4 per (v,g) slab

__global__ __launch_bounds__(256, 8)
void gembedding_broadcast_kernel(const int* __restrict__ GE,
                                 const float* __restrict__ W,   // [3, 64]
                                 const float* __restrict__ b,   // [64]
                                 float4* __restrict__ out) {
    const int pair = blockIdx.x;                 // v*G + g, 0..2047
    // GE values are in [0,3); % 3 kept for parity with the reference.
    int ge = GE[pair] % 3;
    if (ge < 0) ge += 3;                         // defensive (C % vs python %)

    const int t  = threadIdx.x;
    const int dq = t & (DQ - 1);                 // which float4 of the d-row
    const int u0 = t >> 4;                       // 0..15 base u

    const float* wrow = W + ge * D + dq * 4;
    const float* brow = b + dq * 4;
    float4 val;
    val.x = wrow[0] + brow[0];
    val.y = wrow[1] + brow[1];
    val.z = wrow[2] + brow[2];
    val.w = wrow[3] + brow[3];

    float4* base = out + (size_t)pair * ROW_F4 + dq;
    // 512 u-rows, 16 covered per iteration by the 16 u0 lanes -> 32 iters.
    #pragma unroll
    for (int k = 0; k < 32; k++) {
        base[(size_t)(u0 + k * 16) * DQ] = val;
    }
}

extern "C" void kernel_launch(void* const* d_in, const int* in_sizes, int n_in,
                              void* d_out, int out_size) {
    const int*   GE = (const int*)d_in[0];     // [V, G, 1] int32 (see note)
    const float* W  = (const float*)d_in[1];   // [3, D]
    const float* b  = (const float*)d_in[2];   // [D]
    float4* out = (float4*)d_out;

    gembedding_broadcast_kernel<<<V * G, 256>>>(GE, W, b, out);
}

// round 4
// speedup vs baseline: 1.0066x; 1.0066x over previous
#include <cuda_runtime.h>
#include <cuda_bf16.h>
#include <cstdint>

// Problem: out[v][g][u][d] = W[GE[v][g] % 3][d] + b[d]
//   V=512, G=4, D=64, out shape [V,G,V,D] fp32 = 256 MB (pure write-bound).
//
// GE is int32 on-device (JAX x64 disabled).
//
// Grid: one block per (v,g) pair -> 2048 blocks, 256 threads.
// Each thread computes one float4 of the 64-float emb row and stores it
// 32 times (u = tid/16 + 16*k). Per block-iteration k the 8 warps cover
// 16 consecutive u-rows = one contiguous 4KB span; k sweeps the 128KB
// slab sequentially. Stores use __stcs (evict-first streaming) so the
// 256MB output stream doesn't fight for L2 residency and the L2->DRAM
// writeback drain overlaps the store stream.

static constexpr int V = 512;
static constexpr int G = 4;
static constexpr int D = 64;
static constexpr int DQ = D / 4;          // 16 float4 per d-row
static constexpr int ROW_F4 = V * DQ;     // 8192 float4 per (v,g) slab

__global__ __launch_bounds__(256, 8)
void gembedding_broadcast_kernel(const int* __restrict__ GE,
                                 const float* __restrict__ W,   // [3, 64]
                                 const float* __restrict__ b,   // [64]
                                 float4* __restrict__ out) {
    const int pair = blockIdx.x;                 // v*G + g, 0..2047
    const int ge = GE[pair] % 3;                 // values in [0,3)

    const int t  = threadIdx.x;
    const int dq = t & (DQ - 1);                 // which float4 of the d-row
    const int u0 = t >> 4;                       // 0..15 base u

    const float* wrow = W + ge * D + dq * 4;
    const float* brow = b + dq * 4;
    float4 val;
    val.x = wrow[0] + brow[0];
    val.y = wrow[1] + brow[1];
    val.z = wrow[2] + brow[2];
    val.w = wrow[3] + brow[3];

    float4* base = out + (size_t)pair * ROW_F4 + dq;
    // 512 u-rows, 16 covered per iteration -> 32 iterations, all independent.
    #pragma unroll
    for (int k = 0; k < 32; k++) {
        __stcs(&base[(size_t)(u0 + k * 16) * DQ], val);
    }
}

extern "C" void kernel_launch(void* const* d_in, const int* in_sizes, int n_in,
                              void* d_out, int out_size) {
    const int*   GE = (const int*)d_in[0];     // [V, G, 1] int32
    const float* W  = (const float*)d_in[1];   // [3, D]
    const float* b  = (const float*)d_in[2];   // [D]
    float4* out = (float4*)d_out;

    gembedding_broadcast_kernel<<<V * G, 256>>>(GE, W, b, out);
}